// round 3
// baseline (speedup 1.0000x reference)
#include <cuda_runtime.h>

#define NROWS 100000
#define INDIM 256
#define HID   64
#define OUTD  64

// scratch (device globals: no allocation allowed)
__device__ __align__(16) float g_H[(size_t)NROWS * HID];
__device__ __align__(16) float g_O[(size_t)NROWS * OUTD];

// ---------------------------------------------------------------------------
// Kernel 1: H = X @ W1   (100000x256 @ 256x64)
// 256 threads, grid-stride over 64-row tiles. W1 (64KB) + X tile (64KB) in smem.
// Thread t: cols c4 = (t&15)*4, rows rg = (t>>4)*4  -> 4x4 register block.
// Per 4-k chunk: 4 LDS.128 (X, warp-broadcast) + 4 LDS.128 (W, 2-phase)
// feed 64 FFMAs -> FMA-issue-bound, not crossbar-bound.
// ---------------------------------------------------------------------------
__global__ void __launch_bounds__(256, 1) gemm1_kernel(
    const float* __restrict__ X, const float* __restrict__ W1,
    float* __restrict__ H)
{
    extern __shared__ float smem[];
    float* Ws = smem;                 // [256*64]  64KB
    float* Xs = smem + INDIM * HID;   // [64*256]  64KB

    const int tid = threadIdx.x;

    // load W1 once (vectorized)
    {
        const float4* src = reinterpret_cast<const float4*>(W1);
        float4* dst = reinterpret_cast<float4*>(Ws);
        #pragma unroll
        for (int i = tid; i < (INDIM * HID) / 4; i += 256) dst[i] = src[i];
    }

    const int c4 = (tid & 15) * 4;      // 0,4,..,60
    const int rg = (tid >> 4) * 4;      // 0,4,..,60
    const int ntiles = (NROWS + 63) / 64;   // 1563 (last tile: 32 rows)

    for (int tile = blockIdx.x; tile < ntiles; tile += gridDim.x) {
        const int rowBase = tile * 64;
        const int rowsIn  = NROWS - rowBase;   // >=32 for last tile

        __syncthreads();  // Xs free to overwrite (also covers Ws on 1st iter)
        {
            const float4* src =
                reinterpret_cast<const float4*>(X + (size_t)rowBase * INDIM);
            float4* dst = reinterpret_cast<float4*>(Xs);
            #pragma unroll
            for (int i = tid; i < (64 * INDIM) / 4; i += 256) {
                const int r = i >> 6;   // 64 float4 per row
                dst[i] = (r < rowsIn) ? src[i] : make_float4(0.f, 0.f, 0.f, 0.f);
            }
        }
        __syncthreads();

        float acc[4][4];
        #pragma unroll
        for (int r = 0; r < 4; ++r)
            #pragma unroll
            for (int c = 0; c < 4; ++c) acc[r][c] = 0.f;

        const float* xs = Xs + rg * INDIM;

        #pragma unroll 8
        for (int k = 0; k < INDIM; k += 4) {
            float4 w[4];
            #pragma unroll
            for (int j = 0; j < 4; ++j)
                w[j] = *reinterpret_cast<const float4*>(Ws + (k + j) * HID + c4);

            #pragma unroll
            for (int r = 0; r < 4; ++r) {
                const float4 x = *reinterpret_cast<const float4*>(xs + r * INDIM + k);
                acc[r][0] += x.x * w[0].x + x.y * w[1].x + x.z * w[2].x + x.w * w[3].x;
                acc[r][1] += x.x * w[0].y + x.y * w[1].y + x.z * w[2].y + x.w * w[3].y;
                acc[r][2] += x.x * w[0].z + x.y * w[1].z + x.z * w[2].z + x.w * w[3].z;
                acc[r][3] += x.x * w[0].w + x.y * w[1].w + x.z * w[2].w + x.w * w[3].w;
            }
        }

        #pragma unroll
        for (int r = 0; r < 4; ++r) {
            const int row = rowBase + rg + r;
            if (rg + r < rowsIn) {
                *reinterpret_cast<float4*>(H + (size_t)row * HID + c4) =
                    make_float4(acc[r][0], acc[r][1], acc[r][2], acc[r][3]);
            }
        }
    }
}

// ---------------------------------------------------------------------------
// Kernel 2 (fused): O = relu(A @ H) @ W2
// Warp per row; DEG=16 fast path fully unrolled -> 16 gathers in flight.
// ---------------------------------------------------------------------------
__global__ void __launch_bounds__(256) spmm_relu_gemm2_kernel(
    const float* __restrict__ H, const float* __restrict__ W2,
    const float* __restrict__ vals, const int* __restrict__ rowptr,
    const int* __restrict__ colind, float* __restrict__ O)
{
    __shared__ float W2s[HID * OUTD];   // 16KB
    __shared__ float Hs[8][HID];        // per-warp staging

    const int tid = threadIdx.x;
    {
        const float4* src = reinterpret_cast<const float4*>(W2);
        float4* dst = reinterpret_cast<float4*>(W2s);
        #pragma unroll
        for (int i = tid; i < (HID * OUTD) / 4; i += 256) dst[i] = src[i];
    }
    __syncthreads();

    const int warp = tid >> 5;
    const int lane = tid & 31;
    const int row  = blockIdx.x * 8 + warp;
    if (row >= NROWS) return;

    const int start = rowptr[row];
    const int deg   = rowptr[row + 1] - start;

    float ax = 0.f, ay = 0.f;
    if (deg == 16) {
        #pragma unroll
        for (int e = 0; e < 16; ++e) {
            const int   col = __ldg(colind + start + e);
            const float v   = __ldg(vals + start + e);
            const float2 h  =
                *reinterpret_cast<const float2*>(H + (size_t)col * HID + 2 * lane);
            ax += v * h.x;
            ay += v * h.y;
        }
    } else {
        for (int e = start; e < start + deg; ++e) {
            const int   col = colind[e];
            const float v   = vals[e];
            const float2 h  =
                *reinterpret_cast<const float2*>(H + (size_t)col * HID + 2 * lane);
            ax += v * h.x;
            ay += v * h.y;
        }
    }
    ax = fmaxf(ax, 0.f);
    ay = fmaxf(ay, 0.f);

    Hs[warp][2 * lane]     = ax;
    Hs[warp][2 * lane + 1] = ay;
    __syncwarp();

    float ox = 0.f, oy = 0.f;
    #pragma unroll
    for (int j = 0; j < HID; ++j) {
        const float a = Hs[warp][j];
        const float2 w =
            *reinterpret_cast<const float2*>(W2s + j * OUTD + 2 * lane);
        ox += a * w.x;
        oy += a * w.y;
    }

    *reinterpret_cast<float2*>(O + (size_t)row * OUTD + 2 * lane) =
        make_float2(ox, oy);
}

// ---------------------------------------------------------------------------
// Kernel 3: out = A @ O
// ---------------------------------------------------------------------------
__global__ void __launch_bounds__(256) spmm2_kernel(
    const float* __restrict__ O, const float* __restrict__ vals,
    const int* __restrict__ rowptr, const int* __restrict__ colind,
    float* __restrict__ out)
{
    const int tid  = threadIdx.x;
    const int warp = tid >> 5;
    const int lane = tid & 31;
    const int row  = blockIdx.x * 8 + warp;
    if (row >= NROWS) return;

    const int start = rowptr[row];
    const int deg   = rowptr[row + 1] - start;

    float ax = 0.f, ay = 0.f;
    if (deg == 16) {
        #pragma unroll
        for (int e = 0; e < 16; ++e) {
            const int   col = __ldg(colind + start + e);
            const float v   = __ldg(vals + start + e);
            const float2 o  =
                *reinterpret_cast<const float2*>(O + (size_t)col * OUTD + 2 * lane);
            ax += v * o.x;
            ay += v * o.y;
        }
    } else {
        for (int e = start; e < start + deg; ++e) {
            const int   col = colind[e];
            const float v   = vals[e];
            const float2 o  =
                *reinterpret_cast<const float2*>(O + (size_t)col * OUTD + 2 * lane);
            ax += v * o.x;
            ay += v * o.y;
        }
    }

    *reinterpret_cast<float2*>(out + (size_t)row * OUTD + 2 * lane) =
        make_float2(ax, ay);
}

// ---------------------------------------------------------------------------
extern "C" void kernel_launch(void* const* d_in, const int* in_sizes, int n_in,
                              void* d_out, int out_size)
{
    const float* X      = (const float*)d_in[0];
    const float* W1     = (const float*)d_in[1];
    const float* W2     = (const float*)d_in[2];
    const float* vals   = (const float*)d_in[3];
    const int*   rowptr = (const int*)d_in[4];
    const int*   colind = (const int*)d_in[5];
    float*       out    = (float*)d_out;

    float* H; cudaGetSymbolAddress((void**)&H, g_H);
    float* O; cudaGetSymbolAddress((void**)&O, g_O);

    const int smem1 = (INDIM * HID + 64 * INDIM) * sizeof(float);  // 128KB
    static bool attr_set = false;
    if (!attr_set) {
        cudaFuncSetAttribute(gemm1_kernel,
                             cudaFuncAttributeMaxDynamicSharedMemorySize, smem1);
        attr_set = true;
    }

    gemm1_kernel<<<148, 256, smem1>>>(X, W1, H);
    spmm_relu_gemm2_kernel<<<(NROWS + 7) / 8, 256>>>(H, W2, vals, rowptr,
                                                     colind, O);
    spmm2_kernel<<<(NROWS + 7) / 8, 256>>>(O, vals, rowptr, colind, out);
}